// round 7
// baseline (speedup 1.0000x reference)
#include <cuda_runtime.h>

// Rotation_11364483465564 — diagonal phase rotation.
//
// a^T a = diag(0..D-1)  =>  M = expm(i*pi*angle*a^T a) is diagonal,
// M[n] = exp(i*theta*n), theta = fl32(pi_f32 * angle).  kron(M, I2) applies
// phase n to rows 2n and 2n+1 of the (2D, B) complex state.
//
// R6: perfectly balanced single wave. 296 CTAs = exactly 2 per SM (148 SMs)
// x 512 threads, grid-stride over the 2^18 vec4 indices — every SM moves
// identical bytes, eliminating the 2x CTA->SM imbalance present in all
// previous configs (the last untested structural variable). n = gid>>7 is
// warp-uniform, so sincosf stays warp-paced and hidden under the loads.
// No barrier, no smem.
//
// Evidence R0-R5: duration invariant under instruction count (6x), occupancy
// (18-75%), MLP (2-8), write policy, grid shape, sync structure — all
// counters <=16%. Launch-envelope-bound at 16MB; this targets the one
// remaining term (memory-phase tail imbalance).
//
// Precision: arg = fl32(fl32(pi_f32*angle) * n) — bit-identical to the
// reference's expm-input rounding ((float)n exact for n < 2048); accurate
// sincosf (NOT __sincosf — too lossy at |arg| ~ 2e4).

#ifndef ROT_D
#define ROT_D 2048
#endif
#ifndef ROT_B
#define ROT_B 256
#endif

static constexpr int PLANE_FLOATS = 2 * ROT_D * ROT_B;   // 1,048,576
static constexpr int PLANE_VEC4   = PLANE_FLOATS / 4;    // 262,144
static constexpr int NUM_SMS      = 148;
static constexpr int CTAS         = 2 * NUM_SMS;          // 296, 2/SM exactly
static constexpr int THREADS      = 512;
static constexpr int STRIDE       = CTAS * THREADS;       // 151,552

__global__ __launch_bounds__(THREADS)
void rotation_phase_kernel(const float* __restrict__ angle,
                           const float* __restrict__ xr,
                           const float* __restrict__ xi,
                           float* __restrict__ out)
{
    // theta = fl32(pi_f32 * angle) — identical rounding to reference.
    const float theta = 3.14159265358979323846f * __ldg(angle);

    const float4* __restrict__ xr4 = reinterpret_cast<const float4*>(xr);
    const float4* __restrict__ xi4 = reinterpret_cast<const float4*>(xi);
    float4* __restrict__ out4 = reinterpret_cast<float4*>(out);

    const int g = blockIdx.x * THREADS + threadIdx.x;

    // Grid-stride: each thread handles 1 or 2 vec4 indices (both planes).
#pragma unroll
    for (int it = 0; it < 2; ++it) {
        const int gid = g + it * STRIDE;
        if (gid >= PLANE_VEC4) break;

        // Loads first — sincosf below executes in their shadow.
        const float4 r4 = __ldg(xr4 + gid);
        const float4 i4 = __ldg(xi4 + gid);

        // n = gid >> 7 is warp-uniform (warp spans 32 consecutive gids;
        // row boundaries at multiples of 128). (float)n exact for n < 2048.
        const int n = gid >> 7;   // 64 vec4/row, 2 rows per n
        float s, c;
        sincosf(theta * (float)n, &s, &c);   // fl32(theta*n) matches ref arg

        float4 o;
        o.x = fmaf(c, r4.x, -s * i4.x);
        o.y = fmaf(c, r4.y, -s * i4.y);
        o.z = fmaf(c, r4.z, -s * i4.z);
        o.w = fmaf(c, r4.w, -s * i4.w);
        out4[gid] = o;
        o.x = fmaf(s, r4.x,  c * i4.x);
        o.y = fmaf(s, r4.y,  c * i4.y);
        o.z = fmaf(s, r4.z,  c * i4.z);
        o.w = fmaf(s, r4.w,  c * i4.w);
        out4[gid + PLANE_VEC4] = o;
    }
}

extern "C" void kernel_launch(void* const* d_in, const int* in_sizes, int n_in,
                              void* d_out, int out_size)
{
    (void)in_sizes; (void)n_in; (void)out_size;
    const float* angle = (const float*)d_in[0];
    // d_in[1] ('a' matrix) unused: a^T a = diag(0..D-1) analytically.
    const float* xr = (const float*)d_in[2];
    const float* xi = (const float*)d_in[3];
    float* out = (float*)d_out;

    rotation_phase_kernel<<<CTAS, THREADS>>>(angle, xr, xi, out);
}

// round 8
// speedup vs baseline: 1.0099x; 1.0099x over previous
#include <cuda_runtime.h>

// Rotation_11364483465564 — diagonal phase rotation.  (final)
//
// a^T a = diag(0..D-1)  =>  M = expm(i*pi*angle*a^T a) is diagonal,
// M[n] = exp(i*theta*n), theta = fl32(pi_f32 * angle).  kron(M, I2) applies
// phase n to rows 2n and 2n+1 of the (2D, B) complex state.  The problem
// reduces to a 16MB elementwise complex phase multiply; the 16MB 'a' matrix
// is never read.
//
// R7: minimum-CTA single wave. 148 CTAs (exactly 1/SM) x 1024 threads,
// uniform-stride second pass keeps per-SM bytes balanced. Up to 4 LDG.128
// front-batched per thread (MLP=4); n = gid>>7 warp-uniform so sincosf is
// warp-paced and fully hidden under the in-flight loads. No smem, no barrier.
//
// Session evidence (R0-R6): duration invariant (6.34-6.94us) under
// instruction count (6x), occupancy (18-75%), MLP (2-8), write policy,
// sync structure, and wave balance — all utilizations <=19%. The kernel is
// launch-envelope-bound: ~1.5us memory phase + ~5us fixed launch overhead.
//
// Precision: arg = fl32(fl32(pi_f32*angle) * n) — bit-identical to the
// reference's expm-input rounding ((float)n exact for n < 2048); accurate
// sincosf (NOT __sincosf — too lossy at |arg| ~ 2e4).

#ifndef ROT_D
#define ROT_D 2048
#endif
#ifndef ROT_B
#define ROT_B 256
#endif

static constexpr int PLANE_FLOATS = 2 * ROT_D * ROT_B;   // 1,048,576
static constexpr int PLANE_VEC4   = PLANE_FLOATS / 4;    // 262,144
static constexpr int NUM_SMS      = 148;
static constexpr int CTAS         = NUM_SMS;              // 1 CTA per SM
static constexpr int THREADS      = 1024;
static constexpr int STRIDE       = CTAS * THREADS;       // 151,552

__global__ __launch_bounds__(THREADS)
void rotation_phase_kernel(const float* __restrict__ angle,
                           const float* __restrict__ xr,
                           const float* __restrict__ xi,
                           float* __restrict__ out)
{
    // theta = fl32(pi_f32 * angle) — identical rounding to reference.
    const float theta = 3.14159265358979323846f * __ldg(angle);

    const float4* __restrict__ xr4 = reinterpret_cast<const float4*>(xr);
    const float4* __restrict__ xi4 = reinterpret_cast<const float4*>(xi);
    float4* __restrict__ out4 = reinterpret_cast<float4*>(out);

    const int g0 = blockIdx.x * THREADS + threadIdx.x;
    const int g1 = g0 + STRIDE;
    const bool has2 = (g1 < PLANE_VEC4);

    // Front-batch all loads (MLP up to 4) before any math.
    const float4 r0 = __ldg(xr4 + g0);
    const float4 i0 = __ldg(xi4 + g0);
    float4 r1, i1;
    if (has2) {
        r1 = __ldg(xr4 + g1);
        i1 = __ldg(xi4 + g1);
    }

    // n = gid >> 7 is warp-uniform (warp spans 32 consecutive gids; row
    // boundaries at multiples of 128). (float)n exact for n < 2048.
    float s0, c0;
    sincosf(theta * (float)(g0 >> 7), &s0, &c0);  // fl32(theta*n): ref arg

    float4 o;
    o.x = fmaf(c0, r0.x, -s0 * i0.x);
    o.y = fmaf(c0, r0.y, -s0 * i0.y);
    o.z = fmaf(c0, r0.z, -s0 * i0.z);
    o.w = fmaf(c0, r0.w, -s0 * i0.w);
    out4[g0] = o;
    o.x = fmaf(s0, r0.x,  c0 * i0.x);
    o.y = fmaf(s0, r0.y,  c0 * i0.y);
    o.z = fmaf(s0, r0.z,  c0 * i0.z);
    o.w = fmaf(s0, r0.w,  c0 * i0.w);
    out4[g0 + PLANE_VEC4] = o;

    if (has2) {
        float s1, c1;
        sincosf(theta * (float)(g1 >> 7), &s1, &c1);

        o.x = fmaf(c1, r1.x, -s1 * i1.x);
        o.y = fmaf(c1, r1.y, -s1 * i1.y);
        o.z = fmaf(c1, r1.z, -s1 * i1.z);
        o.w = fmaf(c1, r1.w, -s1 * i1.w);
        out4[g1] = o;
        o.x = fmaf(s1, r1.x,  c1 * i1.x);
        o.y = fmaf(s1, r1.y,  c1 * i1.y);
        o.z = fmaf(s1, r1.z,  c1 * i1.z);
        o.w = fmaf(s1, r1.w,  c1 * i1.w);
        out4[g1 + PLANE_VEC4] = o;
    }
}

extern "C" void kernel_launch(void* const* d_in, const int* in_sizes, int n_in,
                              void* d_out, int out_size)
{
    (void)in_sizes; (void)n_in; (void)out_size;
    const float* angle = (const float*)d_in[0];
    // d_in[1] ('a' matrix) unused: a^T a = diag(0..D-1) analytically.
    const float* xr = (const float*)d_in[2];
    const float* xi = (const float*)d_in[3];
    float* out = (float*)d_out;

    rotation_phase_kernel<<<CTAS, THREADS>>>(angle, xr, xi, out);
}